// round 10
// baseline (speedup 1.0000x reference)
#include <cuda_runtime.h>
#include <cuda_bf16.h>
#include <cstdint>

#define TT   1024
#define BSZ  64
#define DD   256
#define HH   256
#define G4   1024            // 4*H
#define TBH  (TT*BSZ*HH)
#define BH   (BSZ*HH)
#define NCTA 128             // 16 clusters x 8 CTAs
#define CLU  8
#define NTHR 1024

typedef unsigned long long ull;

// Scratch (device globals: no runtime allocation allowed)
__device__ float g_Z[(size_t)TT * BSZ * G4];   // [t][b][gate*256+u]  (256 MB)

#define FMA_F32X2(d, a, b, c) \
    asm("fma.rn.f32x2 %0, %1, %2, %3;" : "=l"(d) : "l"(a), "l"(b), "l"(c))
#define ADD_F32X2(d, a, b) \
    asm("add.rn.f32x2 %0, %1, %2;" : "=l"(d) : "l"(a), "l"(b))
#define UNPACK2(lo, hi, s) \
    asm("mov.b64 {%0, %1}, %2;" : "=f"(lo), "=f"(hi) : "l"(s))

// ---------------------------------------------------------------------------
// Phase 1: Z[t][b][g*256+u] = bias_g[u] + sum_k x[t][b][k] * W_g[u*512 + k]
// GEMM M=65536 (t*64+b), N=1024, K=256. BM=128, BN=128, BK=16, 8x8 tiles.
// ---------------------------------------------------------------------------
__global__ __launch_bounds__(256, 2)
void proj_kernel(const float* __restrict__ x,
                 const float* __restrict__ Wf, const float* __restrict__ bf,
                 const float* __restrict__ Wi, const float* __restrict__ bi,
                 const float* __restrict__ Wg, const float* __restrict__ bg,
                 const float* __restrict__ Wo, const float* __restrict__ bo)
{
    __shared__ float As[16 * 132];
    __shared__ float Bs[16 * 132];

    const int tid = threadIdx.x;
    const int tx  = tid & 15;
    const int ty  = tid >> 4;
    const int bm    = blockIdx.y * 128;
    const int gate  = blockIdx.x >> 1;
    const int ucol0 = (blockIdx.x & 1) * 128;

    const float* W    = (gate == 0) ? Wf : (gate == 1) ? Wi : (gate == 2) ? Wg : Wo;
    const float* bias = (gate == 0) ? bf : (gate == 1) ? bi : (gate == 2) ? bg : bo;

    float acc[8][8];
#pragma unroll
    for (int i = 0; i < 8; i++)
#pragma unroll
        for (int j = 0; j < 8; j++) acc[i][j] = 0.f;

    for (int k0 = 0; k0 < 256; k0 += 16) {
#pragma unroll
        for (int it = 0; it < 2; it++) {
            int f4  = tid + it * 256;          // 512 float4 per tile
            int row = f4 >> 2;                 // 0..127
            int kc  = (f4 & 3) << 2;           // 0,4,8,12
            float4 av = *(const float4*)(x + (size_t)(bm + row) * 256 + k0 + kc);
            As[(kc + 0) * 132 + row] = av.x;
            As[(kc + 1) * 132 + row] = av.y;
            As[(kc + 2) * 132 + row] = av.z;
            As[(kc + 3) * 132 + row] = av.w;
            float4 bv = *(const float4*)(W + (size_t)(ucol0 + row) * 512 + k0 + kc);
            Bs[(kc + 0) * 132 + row] = bv.x;
            Bs[(kc + 1) * 132 + row] = bv.y;
            Bs[(kc + 2) * 132 + row] = bv.z;
            Bs[(kc + 3) * 132 + row] = bv.w;
        }
        __syncthreads();
#pragma unroll
        for (int kk = 0; kk < 16; kk++) {
            float4 a0 = *(const float4*)&As[kk * 132 + ty * 8];
            float4 a1 = *(const float4*)&As[kk * 132 + ty * 8 + 4];
            float4 b0 = *(const float4*)&Bs[kk * 132 + tx * 8];
            float4 b1 = *(const float4*)&Bs[kk * 132 + tx * 8 + 4];
            float a[8] = {a0.x, a0.y, a0.z, a0.w, a1.x, a1.y, a1.z, a1.w};
            float b[8] = {b0.x, b0.y, b0.z, b0.w, b1.x, b1.y, b1.z, b1.w};
#pragma unroll
            for (int i = 0; i < 8; i++)
#pragma unroll
                for (int j = 0; j < 8; j++) acc[i][j] += a[i] * b[j];
        }
        __syncthreads();
    }

    float4 q0 = *(const float4*)(bias + ucol0 + tx * 8);
    float4 q1 = *(const float4*)(bias + ucol0 + tx * 8 + 4);
    float bb[8] = {q0.x, q0.y, q0.z, q0.w, q1.x, q1.y, q1.z, q1.w};

#pragma unroll
    for (int i = 0; i < 8; i++) {
        size_t m  = (size_t)(bm + ty * 8 + i);
        float* zp = g_Z + m * 1024 + gate * 256 + ucol0 + tx * 8;
        float4 v0 = {acc[i][0] + bb[0], acc[i][1] + bb[1], acc[i][2] + bb[2], acc[i][3] + bb[3]};
        float4 v1 = {acc[i][4] + bb[4], acc[i][5] + bb[5], acc[i][6] + bb[6], acc[i][7] + bb[7]};
        *(float4*)zp       = v0;
        *(float4*)(zp + 4) = v1;
    }
}

// ---------------------------------------------------------------------------
// Phase 2: cluster-local recurrence. 16 clusters x 8 CTAs x 1024 threads.
// Cluster cid owns batches [4*cid, 4*cid+4). CTA rank r owns hidden units
// [32r, 32r+32) = 128 gate cols (col = uu*4 + gate). h lives in per-CTA SMEM
// (256 units x 4 batches, double buffered), exchanged via DSMEM pushes.
// Sync: SPLIT cluster barrier - arrive (release) right after pushes at loop
// bottom, wait (acquire) at loop top AFTER the next Z prefetch is in flight.
//   warp w: kq = w>>2 (32-k range), cg = w&3 (cols [32cg,32cg+32)), lane=col.
//   Weights as ull k-pairs in regs (wk[16] = 32 regs). h loaded as ull2
//   (pairs already adjacent - NO repacking), 16 FFMA2 per (batch,thread).
//   8-way kq reduction through SMEM partials. Epilogue on 128 threads.
// ---------------------------------------------------------------------------
__device__ __forceinline__ float sig_(float v)  { return __fdividef(1.f, 1.f + __expf(-v)); }
__device__ __forceinline__ float tanh_(float v) { return __fdividef(2.f, 1.f + __expf(-2.f * v)) - 1.f; }

__device__ __forceinline__ uint32_t smem_u32(const void* p) {
    uint32_t a;
    asm("{ .reg .u64 t; cvta.to.shared.u64 t, %1; cvt.u32.u64 %0, t; }"
        : "=r"(a) : "l"(p));
    return a;
}

__device__ __forceinline__ void push_h(uint32_t laddr, int rank, float v) {
    uint32_t ra;
    asm("mapa.shared::cluster.u32 %0, %1, %2;" : "=r"(ra) : "r"(laddr), "r"(rank));
    asm volatile("st.shared::cluster.f32 [%0], %1;" :: "r"(ra), "f"(v));
}

#define CLUSTER_ARRIVE_() \
    asm volatile("barrier.cluster.arrive.aligned;" ::: "memory")
#define CLUSTER_WAIT_() \
    asm volatile("barrier.cluster.wait.aligned;"   ::: "memory")

__global__ __launch_bounds__(NTHR, 1)
void lstm_kernel(const float* __restrict__ Wf, const float* __restrict__ Wi,
                 const float* __restrict__ Wg, const float* __restrict__ Wo,
                 float* __restrict__ out)
{
    __shared__ float hs[2][4][256];     // [buf][bq][k]  (8KB)
    __shared__ float pre4[4][8][128];   // [bq][kq][col] (16KB)

    const int tid  = threadIdx.x;
    const int lane = tid & 31;
    const int w    = tid >> 5;
    const int kq   = w >> 2;            // k-range [32kq, 32kq+32)
    const int cg   = w & 3;             // col-group
    const int lc   = cg * 32 + lane;    // local col 0..127

    uint32_t rank;
    asm("mov.u32 %0, %%cluster_ctarank;" : "=r"(rank));
    const int cid = blockIdx.x >> 3;
    const int b0  = cid * 4;

    // ---- recurrent weights: this thread's col, k in [32kq, 32kq+32) ----
    const int uu = lc >> 2;
    const int gt = lc & 3;
    const float* Ws[4] = {Wf, Wi, Wg, Wo};
    const ull* wrow = (const ull*)(Ws[gt] + (size_t)(rank * 32 + uu) * 512 + 256 + kq * 32);
    ull wk[16];
#pragma unroll
    for (int j = 0; j < 16; j++) wk[j] = wrow[j];

    // zero h buffers
    for (int i = tid; i < 2 * 4 * 256; i += NTHR) ((float*)hs)[i] = 0.f;

    // epilogue identity (threads 0..127): bq = tid>>5, uue = tid&31
    const int bq_e  = tid >> 5;
    const int uu_e  = tid & 31;
    const int bg_e  = b0 + bq_e;                 // global batch
    const int ug_e  = (int)rank * 32 + uu_e;     // global unit
    const uint32_t haddr0 = smem_u32(&hs[0][bq_e][ug_e]);
    const uint32_t haddr1 = smem_u32(&hs[1][bq_e][ug_e]);
    float cstate = 0.f;

    // full prologue sync: hs zeros visible cluster-wide
    CLUSTER_ARRIVE_();
    CLUSTER_WAIT_();

    for (int t = 0; t < TT; t++) {
        // Z prefetch for this step (independent of h) - in flight across wait
        float z0, z1, z2, z3;
        if (tid < 128) {
            const float* zr = g_Z + ((size_t)t * 64 + bg_e) * 1024 + ug_e;
            z0 = __ldcs(zr);
            z1 = __ldcs(zr + 256);
            z2 = __ldcs(zr + 512);
            z3 = __ldcs(zr + 768);
        }

        // wait for step t-1's pushes (matches arrive at bottom of t-1)
        if (t > 0) CLUSTER_WAIT_();

        // ---- GEMM: 4 batches, this thread's col, 32 k's (h as ull2) ----
        const int buf = t & 1;
#pragma unroll
        for (int bq = 0; bq < 4; bq++) {
            const ulonglong2* hp2 = (const ulonglong2*)&hs[buf][bq][kq * 32]; // 8 x ull2
            ull a0 = 0ull, a1 = 0ull;
#pragma unroll
            for (int j = 0; j < 8; j++) {
                ulonglong2 hv = hp2[j];
                FMA_F32X2(a0, wk[2 * j + 0], hv.x, a0);
                FMA_F32X2(a1, wk[2 * j + 1], hv.y, a1);
            }
            ADD_F32X2(a0, a0, a1);
            float lo, hi;
            UNPACK2(lo, hi, a0);
            pre4[bq][kq][lc] = lo + hi;
        }
        __syncthreads();

        // ---- epilogue: 128 threads, one (batch, unit) each ----
        if (tid < 128) {
            float pf = 0.f, pi = 0.f, pg = 0.f, po = 0.f;
#pragma unroll
            for (int q = 0; q < 8; q++) {
                float4 s = *(const float4*)&pre4[bq_e][q][uu_e * 4];
                pf += s.x; pi += s.y; pg += s.z; po += s.w;
            }

            float fg = sig_ (pf + z0);
            float ig = sig_ (pi + z1);
            float gg = tanh_(pg + z2);
            float og = sig_ (po + z3);
            cstate = fg * cstate + ig * gg;
            float h = og * tanh_(cstate);

            out[((size_t)t * 64 + bg_e) * 256 + ug_e] = h;
            if (t == TT - 1) {
                out[TBH + bg_e * 256 + ug_e]      = h;
                out[TBH + BH + bg_e * 256 + ug_e] = cstate;
            }

            // push h to hs[buf^1] of ALL 8 cluster CTAs
            uint32_t ha = (buf ? haddr0 : haddr1);
#pragma unroll
            for (int r = 0; r < CLU; r++) push_h(ha, r, h);
        }

        // per-thread release arrive: each thread's own pushes are ordered
        // before its arrive; wait at next loop top acquires all of them.
        CLUSTER_ARRIVE_();
    }

    // match the final arrive; also ensures no CTA exits while remote
    // stores targeting it may still be in flight.
    CLUSTER_WAIT_();
}

// ---------------------------------------------------------------------------
// Launch
// ---------------------------------------------------------------------------
extern "C" void kernel_launch(void* const* d_in, const int* in_sizes, int n_in,
                              void* d_out, int out_size)
{
    const float* x  = (const float*)d_in[0];
    const float* Wf = (const float*)d_in[1];
    const float* bf = (const float*)d_in[2];
    const float* Wi = (const float*)d_in[3];
    const float* bi = (const float*)d_in[4];
    const float* Wg = (const float*)d_in[5];
    const float* bg = (const float*)d_in[6];
    const float* Wo = (const float*)d_in[7];
    const float* bo = (const float*)d_in[8];
    float* out = (float*)d_out;

    proj_kernel<<<dim3(8, 512), 256>>>(x, Wf, bf, Wi, bi, Wg, bg, Wo, bo);

    cudaLaunchConfig_t cfg = {};
    cfg.gridDim  = dim3(NCTA, 1, 1);
    cfg.blockDim = dim3(NTHR, 1, 1);
    cfg.dynamicSmemBytes = 0;
    cudaLaunchAttribute attrs[1];
    attrs[0].id = cudaLaunchAttributeClusterDimension;
    attrs[0].val.clusterDim.x = CLU;
    attrs[0].val.clusterDim.y = 1;
    attrs[0].val.clusterDim.z = 1;
    cfg.attrs = attrs;
    cfg.numAttrs = 1;
    cudaLaunchKernelEx(&cfg, lstm_kernel, Wf, Wi, Wg, Wo, out);
}